// round 12
// baseline (speedup 1.0000x reference)
#include <cuda_runtime.h>
#include <cuda_bf16.h>
#include <math.h>
#include <stdint.h>

typedef __nv_bfloat16 bf16;

namespace {
constexpr int Bb=8, Ll=2048, Dd=1024, QKd=128, UVd=2048;
constexpr int MT = Bb*Ll;
constexpr long long O_ELEMS = (long long)MT*Dd;
constexpr long long ATTN_ELEMS = (long long)Bb*Ll*Ll;
// smem: 3 stages x 4 planes x [128 rows][20 uint32 (16 pairs + 4 pad)]
constexpr int PLANE_BYTES = 128*20*4;          // 10240
constexpr int STAGE_BYTES = 4*PLANE_BYTES;     // 40960
constexpr int SMEM_BYTES  = 3*STAGE_BYTES;     // 122880
}

// ------------------------- scratch (__device__ globals) --------------------
__device__ __align__(128) float g_qk  [MT*QKd];
__device__ __align__(128) bf16  g_qh[MT*QKd], g_ql[MT*QKd], g_kh[MT*QKd], g_kl[MT*QKd];
__device__ __align__(128) bf16  g_Qh[MT*Dd], g_Ql[MT*Dd], g_Vh[MT*Dd], g_Vl[MT*Dd];
__device__ __align__(128) bf16  g_Uh[MT*Dd], g_Ul[MT*Dd];
__device__ __align__(128) bf16  g_WqkTh[QKd*Dd], g_WqkTl[QKd*Dd];
__device__ __align__(128) bf16  g_WvTh[UVd*Dd],  g_WvTl[UVd*Dd];
__device__ __align__(128) bf16  g_WuTh[UVd*Dd],  g_WuTl[UVd*Dd];
__device__ __align__(128) bf16  g_WoTh[Dd*UVd],  g_WoTl[Dd*UVd];
__device__ __align__(128) bf16  g_vTh[(long long)Bb*UVd*Ll], g_vTl[(long long)Bb*UVd*Ll];
__device__ __align__(128) float g_ug  [(long long)MT*UVd];
__device__ __align__(128) float g_attn[(long long)Bb*Ll*Ll];
__device__ __align__(128) bf16  g_ah[(long long)Bb*Ll*Ll], g_al[(long long)Bb*Ll*Ll];
__device__ __align__(128) bf16  g_gh[(long long)MT*UVd],   g_gl[(long long)MT*UVd];

// ------------------------------ helpers ------------------------------------
__device__ __forceinline__ uint32_t smem_u32(const void* p){
    uint32_t a; asm("{ .reg .u64 t; cvta.to.shared.u64 t, %1; cvt.u32.u64 %0, t; }":"=r"(a):"l"(p)); return a;
}
__device__ __forceinline__ float gelu_f(float x){
    float z = 0.7978845608028654f*(x + 0.044715f*x*x*x);
    float e = __expf(-2.0f*fabsf(z));
    float t = (1.0f-e)/(1.0f+e);
    return 0.5f*x*(1.0f+copysignf(t,z));
}
__device__ __forceinline__ uint32_t pack2(float a, float b){
    __nv_bfloat162 t = __halves2bfloat162(__float2bfloat16(a), __float2bfloat16(b));
    return *reinterpret_cast<uint32_t*>(&t);
}
__device__ __forceinline__ float bf_hi(float x){ return __bfloat162float(__float2bfloat16(x)); }

__device__ __forceinline__ void cp16(uint32_t d, const void* s){
    asm volatile("cp.async.cg.shared.global [%0], [%1], 16;" :: "r"(d), "l"(s));
}
__device__ __forceinline__ void cpcommit(){ asm volatile("cp.async.commit_group;" ::: "memory"); }
template<int N> __device__ __forceinline__ void cpwait(){ asm volatile("cp.async.wait_group %0;"::"n"(N):"memory"); }

__device__ __forceinline__ void mma16816(float* c, const unsigned int* a,
                                         const unsigned int* b) {
    asm volatile(
        "mma.sync.aligned.m16n8k16.row.col.f32.bf16.bf16.f32 "
        "{%0,%1,%2,%3}, {%4,%5,%6,%7}, {%8,%9}, {%0,%1,%2,%3};"
        : "+f"(c[0]), "+f"(c[1]), "+f"(c[2]), "+f"(c[3])
        : "r"(a[0]), "r"(a[1]), "r"(a[2]), "r"(a[3]), "r"(b[0]), "r"(b[1]));
}
__device__ __forceinline__ void ldsm4(uint32_t* r, uint32_t a){
    asm volatile("ldmatrix.sync.aligned.m8n8.x4.shared.b16 {%0,%1,%2,%3}, [%4];"
        : "=r"(r[0]), "=r"(r[1]), "=r"(r[2]), "=r"(r[3]) : "r"(a));
}

// ===========================================================================
// HMMA split-bf16 GEMM: C[M,N] = A @ B^T from pre-split hi/lo bf16 planes.
// A: [M][K] row-major planes; B: [N][K] n-major planes. BK=32, 3-stage cp.async,
// ldmatrix fragment loads.
// EPI: 0 gelu(acc+bias)->f32 | 1 acc+bias->f32 | 2 acc*alpha->f32
//      3 acc*gate -> hi/lo planes | 4 gelu(acc+bias) -> transposed hi/lo
// ===========================================================================
template<int EPI>
__global__ __launch_bounds__(256,1) void gemm_hmma(
    int K, int N,
    const bf16* __restrict__ Ah, const bf16* __restrict__ Al, long long sA,
    const bf16* __restrict__ Bh, const bf16* __restrict__ Bl, long long sB,
    float* __restrict__ Cf, long long sC,
    bf16* __restrict__ Ch, bf16* __restrict__ Cl, long long sCh,
    const float* __restrict__ bias,
    const float* __restrict__ gate, long long sG, float alpha)
{
    extern __shared__ __align__(16) char smem[];
    const uint32_t sb = smem_u32(smem);

    const int tid  = threadIdx.x;
    const int wid  = tid >> 5;
    const int lane = tid & 31;
    const int g    = lane >> 2;           // 0..7
    const int tg   = lane & 3;            // 0..3
    const int wm   = wid >> 2;            // 0..1 -> 64-row slab
    const int wn   = wid & 3;             // 0..3 -> 32-col slab
    const int lr   = lane & 15;           // ldmatrix row-lane
    const int lh   = lane >> 4;           // ldmatrix 16B-half

    const long long bz = blockIdx.z;
    Ah += bz*sA; Al += bz*sA; Bh += bz*sB; Bl += bz*sB;
    if (EPI<=2) Cf += bz*sC;
    if (EPI==3){ Ch += bz*sCh; Cl += bz*sCh; gate += bz*sG; }
    const int rowBase = blockIdx.y*128, colBase = blockIdx.x*128;

    float acc[4][4][4];
#pragma unroll
    for (int i=0;i<4;i++)
#pragma unroll
        for (int j=0;j<4;j++)
#pragma unroll
            for (int e=0;e<4;e++) acc[i][j][e] = 0.0f;

    const int NC = K >> 5;                // K/32 chunks

    auto load_stage = [&](int kc, int s){
        const uint32_t st = sb + s*STAGE_BYTES;
        const long long k0 = (long long)kc << 5;
#pragma unroll
        for (int t=0;t<8;t++){
            int id    = tid + (t&1)*256;            // 0..511
            int plane = t>>1;                       // 0..3
            int r     = id >> 2;                    // 0..127
            int c16   = id & 3;                     // 16B unit within 64B row
            uint32_t dst = st + plane*PLANE_BYTES + r*80 + c16*16;
            const bf16* src;
            if      (plane==0) src = Ah + (long long)(rowBase+r)*K + k0 + c16*8;
            else if (plane==1) src = Al + (long long)(rowBase+r)*K + k0 + c16*8;
            else if (plane==2) src = Bh + (long long)(colBase+r)*K + k0 + c16*8;
            else               src = Bl + (long long)(colBase+r)*K + k0 + c16*8;
            cp16(dst, src);
        }
        cpcommit();
    };

    load_stage(0, 0);
    load_stage(1, 1);
    cpwait<1>();
    __syncthreads();

    for (int c=0; c<NC; c++){
        const int s = c - (c/3)*3;                  // c % 3
        const uint32_t st = sb + s*STAGE_BYTES;
        // per-warp ldmatrix base addresses for this stage
        const uint32_t aBase = st + (uint32_t)((wm*64 + lr)*80 + lh*16);
        const uint32_t bBase = st + 2*PLANE_BYTES + (uint32_t)((wn*32 + lr)*80 + lh*16);

#pragma unroll
        for (int ks=0; ks<2; ks++){
            const uint32_t ko = ks*32;              // byte offset within row
            unsigned int ah[4][4], al[4][4], bh[4][2], bl[4][2];
#pragma unroll
            for (int i=0;i<4;i++){
                ldsm4(ah[i], aBase + ko + i*16*80);
                ldsm4(al[i], aBase + PLANE_BYTES + ko + i*16*80);
            }
#pragma unroll
            for (int jj=0;jj<2;jj++){
                uint32_t t4[4];
                ldsm4(t4, bBase + ko + jj*16*80);
                bh[2*jj][0]=t4[0]; bh[2*jj+1][0]=t4[1];
                bh[2*jj][1]=t4[2]; bh[2*jj+1][1]=t4[3];
                ldsm4(t4, bBase + PLANE_BYTES + ko + jj*16*80);
                bl[2*jj][0]=t4[0]; bl[2*jj+1][0]=t4[1];
                bl[2*jj][1]=t4[2]; bl[2*jj+1][1]=t4[3];
            }
#pragma unroll
            for (int i=0;i<4;i++)
#pragma unroll
                for (int j=0;j<4;j++){
                    mma16816(acc[i][j], ah[i], bh[j]);
                    mma16816(acc[i][j], ah[i], bl[j]);
                    mma16816(acc[i][j], al[i], bh[j]);
                }
        }

        if (c+1 < NC){
            if (c+2 < NC){
                int s2 = (c+2) - ((c+2)/3)*3;
                load_stage(c+2, s2);
                cpwait<1>();
            } else {
                cpwait<0>();
            }
            __syncthreads();
        }
    }

    // ------------------------------- epilogue ------------------------------
    if (EPI<=3){
#pragma unroll
        for (int i=0;i<4;i++){
#pragma unroll
            for (int j=0;j<4;j++){
                const int r0 = rowBase + wm*64 + i*16 + g;
                const int c0 = colBase + wn*32 + j*8 + tg*2;
#pragma unroll
                for (int h=0;h<2;h++){
                    const int r = r0 + h*8;
                    float v0 = acc[i][j][2*h+0];
                    float v1 = acc[i][j][2*h+1];
                    if (EPI==0){
                        v0 = gelu_f(v0 + bias[c0]);
                        v1 = gelu_f(v1 + bias[c0+1]);
                        *(float2*)(Cf + (long long)r*N + c0) = make_float2(v0, v1);
                    } else if (EPI==1){
                        v0 += bias[c0]; v1 += bias[c0+1];
                        *(float2*)(Cf + (long long)r*N + c0) = make_float2(v0, v1);
                    } else if (EPI==2){
                        *(float2*)(Cf + (long long)r*N + c0) = make_float2(v0*alpha, v1*alpha);
                    } else {
                        const long long off = (long long)r*N + c0;
                        const float2 gg = *(const float2*)(gate + off);
                        float x0 = v0*gg.x, x1 = v1*gg.y;
                        *(uint32_t*)(Ch + off) = pack2(x0, x1);
                        *(uint32_t*)(Cl + off) = pack2(x0 - bf_hi(x0), x1 - bf_hi(x1));
                    }
                }
            }
        }
    } else {
        // EPI==4: gelu(acc+bias) -> transposed hi/lo planes [Bb][UVd][Ll].
        // Stage the 128x128 tile through smem (reusing pipeline buffers).
        __syncthreads();                          // all warps done with stages
        float* tb = (float*)smem;                 // [128 n][132 m] f32
#pragma unroll
        for (int i=0;i<4;i++){
#pragma unroll
            for (int j=0;j<4;j++){
                const int cl0 = wn*32 + j*8 + tg*2;
                const int rl0 = wm*64 + i*16 + g;
#pragma unroll
                for (int h=0;h<2;h++){
                    const int rl = rl0 + h*8;
                    float x0 = gelu_f(acc[i][j][2*h+0] + bias[colBase+cl0]);
                    float x1 = gelu_f(acc[i][j][2*h+1] + bias[colBase+cl0+1]);
                    tb[cl0*132 + rl]     = x0;
                    tb[(cl0+1)*132 + rl] = x1;
                }
            }
        }
        __syncthreads();
        const int b  = rowBase >> 11;
        const int l0 = rowBase & (Ll-1);
#pragma unroll
        for (int i=0;i<16;i++){
            const int nl = wid*16 + i;
            float4 v = *(float4*)&tb[nl*132 + lane*4];
            long long off = ((long long)b*UVd + colBase + nl)*Ll + l0 + lane*4;
            *(uint2*)(Ch + off) = make_uint2(pack2(v.x,v.y), pack2(v.z,v.w));
            *(uint2*)(Cl + off) = make_uint2(pack2(v.x-bf_hi(v.x), v.y-bf_hi(v.y)),
                                             pack2(v.z-bf_hi(v.z), v.w-bf_hi(v.w)));
        }
    }
}

// --------------------------- small kernels ---------------------------------
__global__ void conv_hl(const float4* __restrict__ x, uint2* __restrict__ h,
                        uint2* __restrict__ l, int n4)
{
    int i = blockIdx.x*256 + threadIdx.x;
    if (i >= n4) return;
    float4 v = x[i];
    h[i] = make_uint2(pack2(v.x,v.y), pack2(v.z,v.w));
    l[i] = make_uint2(pack2(v.x-bf_hi(v.x),v.y-bf_hi(v.y)),
                      pack2(v.z-bf_hi(v.z),v.w-bf_hi(v.w)));
}

__global__ void convT_hl(const float* __restrict__ W, bf16* __restrict__ th,
                         bf16* __restrict__ tl, int Rw, int Cw)
{
    __shared__ float t[32][33];
    int rB = blockIdx.y*32, cB = blockIdx.x*32;
    t[threadIdx.y][threadIdx.x] = W[(long long)(rB+threadIdx.y)*Cw + cB + threadIdx.x];
    __syncthreads();
    float v = t[threadIdx.x][threadIdx.y];
    long long o = (long long)(cB+threadIdx.y)*Rw + rB + threadIdx.x;
    th[o] = __float2bfloat16(v);
    tl[o] = __float2bfloat16(v - bf_hi(v));
}

__global__ void rope_hl(const float* __restrict__ qk,
                        const float* __restrict__ gq, const float* __restrict__ betq,
                        const float* __restrict__ gk, const float* __restrict__ betk,
                        bf16* __restrict__ qh, bf16* __restrict__ ql,
                        bf16* __restrict__ kh, bf16* __restrict__ kl)
{
    int idx = blockIdx.x*256 + threadIdx.x;
    if (idx >= MT*64) return;
    int p = idx&63, row = idx>>6, l = row&(Ll-1);
    float invf = powf(10000.0f, -(float)(2*p)/128.0f);
    float s, c; sincosf((float)l*invf, &s, &c);
    float2 v = ((const float2*)qk)[idx];
    float q1 = v.x*gq[2*p]+betq[2*p], q2 = v.y*gq[2*p+1]+betq[2*p+1];
    float a = q1*c-q2*s, b = q1*s+q2*c;
    ((uint32_t*)qh)[idx] = pack2(a,b);
    ((uint32_t*)ql)[idx] = pack2(a-bf_hi(a), b-bf_hi(b));
    float k1 = v.x*gk[2*p]+betk[2*p], k2 = v.y*gk[2*p+1]+betk[2*p+1];
    a = k1*c-k2*s; b = k1*s+k2*c;
    ((uint32_t*)kh)[idx] = pack2(a,b);
    ((uint32_t*)kl)[idx] = pack2(a-bf_hi(a), b-bf_hi(b));
}

__global__ void softmax_hl(float* __restrict__ attn,
                           bf16* __restrict__ ah, bf16* __restrict__ al)
{
    const long long row = blockIdx.x;
    float* p = attn + row*Ll;
    const int tid = threadIdx.x;
    __shared__ float red[256];

    float m = -INFINITY;
    for (int i=tid;i<Ll;i+=256) m = fmaxf(m, p[i]);
    red[tid]=m; __syncthreads();
    for (int s=128;s>0;s>>=1){ if(tid<s) red[tid]=fmaxf(red[tid],red[tid+s]); __syncthreads(); }
    m = red[0]; __syncthreads();

    float sum = 0.0f;
    for (int i=tid;i<Ll;i+=256){ float e=__expf(p[i]-m); p[i]=e; sum+=e; }
    red[tid]=sum; __syncthreads();
    for (int s=128;s>0;s>>=1){ if(tid<s) red[tid]+=red[tid+s]; __syncthreads(); }
    float r = 1.0f/red[0];

    uint32_t* wh = (uint32_t*)ah + row*(Ll/2);
    uint32_t* wl = (uint32_t*)al + row*(Ll/2);
    for (int i=tid;i<Ll/2;i+=256){
        float2 e = ((float2*)p)[i];
        float v0=e.x*r, v1=e.y*r;
        ((float2*)p)[i] = make_float2(v0,v1);
        wh[i] = pack2(v0,v1);
        wl[i] = pack2(v0-bf_hi(v0), v1-bf_hi(v1));
    }
}

// ---------------------------------------------------------------------------
extern "C" void kernel_launch(void* const* d_in, const int* in_sizes, int n_in,
                              void* d_out, int out_size)
{
    const float* u       = (const float*)d_in[0];
    const float* queries = (const float*)d_in[1];
    const float* values  = (const float*)d_in[3];
    const float* Wqk  = (const float*)d_in[4];
    const float* bqk  = (const float*)d_in[5];
    const float* gq   = (const float*)d_in[6];
    const float* betq = (const float*)d_in[7];
    const float* gk   = (const float*)d_in[8];
    const float* betk = (const float*)d_in[9];
    const float* Wv   = (const float*)d_in[10];
    const float* bv   = (const float*)d_in[11];
    const float* Wu   = (const float*)d_in[12];
    const float* bu   = (const float*)d_in[13];
    const float* Wo   = (const float*)d_in[14];
    const float* bo   = (const float*)d_in[15];

    float *qk, *ug, *attn_s;
    bf16 *qh,*ql,*kh,*kl,*Qh,*Ql,*Vh,*Vl,*Uh,*Ul;
    bf16 *WqkTh,*WqkTl,*WvTh,*WvTl,*WuTh,*WuTl,*WoTh,*WoTl;
    bf16 *vTh,*vTl,*ah,*al,*gh,*gl;
    cudaGetSymbolAddress((void**)&qk, g_qk);
    cudaGetSymbolAddress((void**)&qh, g_qh);   cudaGetSymbolAddress((void**)&ql, g_ql);
    cudaGetSymbolAddress((void**)&kh, g_kh);   cudaGetSymbolAddress((void**)&kl, g_kl);
    cudaGetSymbolAddress((void**)&Qh, g_Qh);   cudaGetSymbolAddress((void**)&Ql, g_Ql);
    cudaGetSymbolAddress((void**)&Vh, g_Vh);   cudaGetSymbolAddress((void**)&Vl, g_Vl);
    cudaGetSymbolAddress((void**)&Uh, g_Uh);   cudaGetSymbolAddress((void**)&Ul, g_Ul);
    cudaGetSymbolAddress((void**)&WqkTh, g_WqkTh); cudaGetSymbolAddress((void**)&WqkTl, g_WqkTl);
    cudaGetSymbolAddress((void**)&WvTh, g_WvTh);   cudaGetSymbolAddress((void**)&WvTl, g_WvTl);
    cudaGetSymbolAddress((void**)&WuTh, g_WuTh);   cudaGetSymbolAddress((void**)&WuTl, g_WuTl);
    cudaGetSymbolAddress((void**)&WoTh, g_WoTh);   cudaGetSymbolAddress((void**)&WoTl, g_WoTl);
    cudaGetSymbolAddress((void**)&vTh, g_vTh);     cudaGetSymbolAddress((void**)&vTl, g_vTl);
    cudaGetSymbolAddress((void**)&ug, g_ug);
    cudaGetSymbolAddress((void**)&attn_s, g_attn);
    cudaGetSymbolAddress((void**)&ah, g_ah);   cudaGetSymbolAddress((void**)&al, g_al);
    cudaGetSymbolAddress((void**)&gh, g_gh);   cudaGetSymbolAddress((void**)&gl, g_gl);

    float* o_out = (float*)d_out;
    float* attn = ((long long)out_size >= O_ELEMS + ATTN_ELEMS)
                      ? (o_out + O_ELEMS) : attn_s;

    cudaFuncSetAttribute(gemm_hmma<0>, cudaFuncAttributeMaxDynamicSharedMemorySize, SMEM_BYTES);
    cudaFuncSetAttribute(gemm_hmma<1>, cudaFuncAttributeMaxDynamicSharedMemorySize, SMEM_BYTES);
    cudaFuncSetAttribute(gemm_hmma<2>, cudaFuncAttributeMaxDynamicSharedMemorySize, SMEM_BYTES);
    cudaFuncSetAttribute(gemm_hmma<3>, cudaFuncAttributeMaxDynamicSharedMemorySize, SMEM_BYTES);
    cudaFuncSetAttribute(gemm_hmma<4>, cudaFuncAttributeMaxDynamicSharedMemorySize, SMEM_BYTES);

    const long long sQK = (long long)Ll*QKd, sAT = (long long)Ll*Ll;
    const long long sUV = (long long)Ll*UVd, sVT = (long long)UVd*Ll;
    const int n4 = MT*Dd/4;

    // input + weight conversion to hi/lo planes
    conv_hl<<<(n4+255)/256,256>>>((const float4*)queries,(uint2*)Qh,(uint2*)Ql,n4);
    conv_hl<<<(n4+255)/256,256>>>((const float4*)values, (uint2*)Vh,(uint2*)Vl,n4);
    conv_hl<<<(n4+255)/256,256>>>((const float4*)u,      (uint2*)Uh,(uint2*)Ul,n4);
    convT_hl<<<dim3(QKd/32, Dd/32), dim3(32,32)>>>(Wqk, WqkTh, WqkTl, Dd, QKd);
    convT_hl<<<dim3(UVd/32, Dd/32), dim3(32,32)>>>(Wv,  WvTh,  WvTl,  Dd, UVd);
    convT_hl<<<dim3(UVd/32, Dd/32), dim3(32,32)>>>(Wu,  WuTh,  WuTl,  Dd, UVd);
    convT_hl<<<dim3(Dd/32, UVd/32), dim3(32,32)>>>(Wo,  WoTh,  WoTl,  UVd, Dd);

    // 1) qk = gelu(queries @ Wqk + bqk)            [16384 x 128]
    gemm_hmma<0><<<dim3(1,128,1),256,SMEM_BYTES>>>(Dd, QKd, Qh,Ql,0, WqkTh,WqkTl,0,
        qk,0, nullptr,nullptr,0, bqk, nullptr,0, 0.f);
    // 2) rope -> q/k hi-lo planes
    rope_hl<<<(MT*64+255)/256,256>>>(qk, gq,betq, gk,betk, qh,ql, kh,kl);
    // 3) v^T planes = gelu(values @ Wv + bv)^T     [8][2048][2048]
    gemm_hmma<4><<<dim3(UVd/128,128,1),256,SMEM_BYTES>>>(Dd, UVd, Vh,Vl,0, WvTh,WvTl,0,
        nullptr,0, vTh,vTl,0, bv, nullptr,0, 0.f);
    // 4) ug = gelu(u @ Wu + bu)                    [16384 x 2048] f32
    gemm_hmma<0><<<dim3(UVd/128,128,1),256,SMEM_BYTES>>>(Dd, UVd, Uh,Ul,0, WuTh,WuTl,0,
        ug,0, nullptr,nullptr,0, bu, nullptr,0, 0.f);
    // 5) scores = q @ k^T / sqrt(128)              [8 x 2048 x 2048]
    gemm_hmma<2><<<dim3(Ll/128,Ll/128,Bb),256,SMEM_BYTES>>>(QKd, Ll, qh,ql,sQK, kh,kl,sQK,
        attn,sAT, nullptr,nullptr,0, nullptr, nullptr,0, 0.08838834764831845f);
    // 6) softmax rows -> attn f32 + hi/lo planes
    softmax_hl<<<MT,256>>>(attn, ah, al);
    // 7) gated planes = ug * (attn @ v)            [8 x 2048 x 2048]
    gemm_hmma<3><<<dim3(UVd/128,Ll/128,Bb),256,SMEM_BYTES>>>(Ll, UVd, ah,al,sAT, vTh,vTl,sVT,
        nullptr,0, gh,gl,sUV, nullptr, ug,sUV, 0.f);
    // 8) o = gated @ Wo + bo                       [16384 x 1024]
    gemm_hmma<1><<<dim3(Dd/128,128,1),256,SMEM_BYTES>>>(UVd, Dd, gh,gl,0, WoTh,WoTl,0,
        o_out,0, nullptr,nullptr,0, bo, nullptr,0, 0.f);
}

// round 14
// speedup vs baseline: 1.1509x; 1.1509x over previous
#include <cuda_runtime.h>
#include <cuda_bf16.h>
#include <math.h>
#include <stdint.h>

typedef __nv_bfloat16 bf16;

namespace {
constexpr int Bb=8, Ll=2048, Dd=1024, QKd=128, UVd=2048;
constexpr int MT = Bb*Ll;
constexpr long long O_ELEMS = (long long)MT*Dd;
constexpr long long ATTN_ELEMS = (long long)Bb*Ll*Ll;
// smem: 2 stages x 4 planes x [128 rows][20 uint32 (16 pairs + 4 pad)]
constexpr int PLANE_BYTES = 128*20*4;          // 10240
constexpr int STAGE_BYTES = 4*PLANE_BYTES;     // 40960
constexpr int SMEM_BYTES  = 2*STAGE_BYTES;     // 81920  (2 CTAs/SM fit)
}

// ------------------------- scratch (__device__ globals) --------------------
__device__ __align__(128) float g_qk  [MT*QKd];
__device__ __align__(128) bf16  g_qh[MT*QKd], g_ql[MT*QKd], g_kh[MT*QKd], g_kl[MT*QKd];
__device__ __align__(128) bf16  g_Qh[MT*Dd], g_Ql[MT*Dd], g_Vh[MT*Dd], g_Vl[MT*Dd];
__device__ __align__(128) bf16  g_Uh[MT*Dd], g_Ul[MT*Dd];
__device__ __align__(128) bf16  g_WqkTh[QKd*Dd], g_WqkTl[QKd*Dd];
__device__ __align__(128) bf16  g_WvTh[UVd*Dd],  g_WvTl[UVd*Dd];
__device__ __align__(128) bf16  g_WuTh[UVd*Dd],  g_WuTl[UVd*Dd];
__device__ __align__(128) bf16  g_WoTh[Dd*UVd],  g_WoTl[Dd*UVd];
__device__ __align__(128) bf16  g_vTh[(long long)Bb*UVd*Ll], g_vTl[(long long)Bb*UVd*Ll];
__device__ __align__(128) float g_ug  [(long long)MT*UVd];
__device__ __align__(128) float g_attn[(long long)Bb*Ll*Ll];
__device__ __align__(128) bf16  g_ah[(long long)Bb*Ll*Ll], g_al[(long long)Bb*Ll*Ll];
__device__ __align__(128) bf16  g_gh[(long long)MT*UVd],   g_gl[(long long)MT*UVd];

// ------------------------------ helpers ------------------------------------
__device__ __forceinline__ uint32_t smem_u32(const void* p){
    uint32_t a; asm("{ .reg .u64 t; cvta.to.shared.u64 t, %1; cvt.u32.u64 %0, t; }":"=r"(a):"l"(p)); return a;
}
__device__ __forceinline__ float gelu_f(float x){
    float z = 0.7978845608028654f*(x + 0.044715f*x*x*x);
    float e = __expf(-2.0f*fabsf(z));
    float t = (1.0f-e)/(1.0f+e);
    return 0.5f*x*(1.0f+copysignf(t,z));
}
__device__ __forceinline__ uint32_t pack2(float a, float b){
    __nv_bfloat162 t = __halves2bfloat162(__float2bfloat16(a), __float2bfloat16(b));
    return *reinterpret_cast<uint32_t*>(&t);
}
__device__ __forceinline__ float bf_hi(float x){ return __bfloat162float(__float2bfloat16(x)); }

__device__ __forceinline__ void cp16(uint32_t d, const void* s){
    asm volatile("cp.async.cg.shared.global [%0], [%1], 16;" :: "r"(d), "l"(s));
}
__device__ __forceinline__ void cpcommit(){ asm volatile("cp.async.commit_group;" ::: "memory"); }
template<int N> __device__ __forceinline__ void cpwait(){ asm volatile("cp.async.wait_group %0;"::"n"(N):"memory"); }

__device__ __forceinline__ void mma16816(float* c, const unsigned int* a,
                                         const unsigned int* b) {
    asm volatile(
        "mma.sync.aligned.m16n8k16.row.col.f32.bf16.bf16.f32 "
        "{%0,%1,%2,%3}, {%4,%5,%6,%7}, {%8,%9}, {%0,%1,%2,%3};"
        : "+f"(c[0]), "+f"(c[1]), "+f"(c[2]), "+f"(c[3])
        : "r"(a[0]), "r"(a[1]), "r"(a[2]), "r"(a[3]), "r"(b[0]), "r"(b[1]));
}
__device__ __forceinline__ void ldsm4(uint32_t* r, uint32_t a){
    asm volatile("ldmatrix.sync.aligned.m8n8.x4.shared.b16 {%0,%1,%2,%3}, [%4];"
        : "=r"(r[0]), "=r"(r[1]), "=r"(r[2]), "=r"(r[3]) : "r"(a));
}

// ===========================================================================
// HMMA split-bf16 GEMM: C[M,N] = A @ B^T from pre-split hi/lo bf16 planes.
// A: [M][K] row-major planes; B: [N][K] n-major planes. BK=32, 2-stage cp.async
// (proven R7 control flow), ldmatrix fragment loads, 2 CTAs/SM.
// EPI: 0 gelu(acc+bias)->f32 | 1 acc+bias->f32 | 2 acc*alpha->f32
//      3 acc*gate -> hi/lo planes | 4 gelu(acc+bias) -> transposed hi/lo
// ===========================================================================
template<int EPI>
__global__ __launch_bounds__(256,2) void gemm_hmma(
    int K, int N,
    const bf16* __restrict__ Ah, const bf16* __restrict__ Al, long long sA,
    const bf16* __restrict__ Bh, const bf16* __restrict__ Bl, long long sB,
    float* __restrict__ Cf, long long sC,
    bf16* __restrict__ Ch, bf16* __restrict__ Cl, long long sCh,
    const float* __restrict__ bias,
    const float* __restrict__ gate, long long sG, float alpha)
{
    extern __shared__ __align__(16) char smem[];
    const uint32_t sb = smem_u32(smem);

    const int tid  = threadIdx.x;
    const int wid  = tid >> 5;
    const int lane = tid & 31;
    const int g    = lane >> 2;           // 0..7
    const int tg   = lane & 3;            // 0..3
    const int wm   = wid >> 2;            // 0..1 -> 64-row slab
    const int wn   = wid & 3;             // 0..3 -> 32-col slab
    const int lr   = lane & 15;           // ldmatrix row-lane
    const int lh   = lane >> 4;           // ldmatrix 16B-half

    const long long bz = blockIdx.z;
    Ah += bz*sA; Al += bz*sA; Bh += bz*sB; Bl += bz*sB;
    if (EPI<=2) Cf += bz*sC;
    if (EPI==3){ Ch += bz*sCh; Cl += bz*sCh; gate += bz*sG; }
    const int rowBase = blockIdx.y*128, colBase = blockIdx.x*128;

    float acc[4][4][4];
#pragma unroll
    for (int i=0;i<4;i++)
#pragma unroll
        for (int j=0;j<4;j++)
#pragma unroll
            for (int e=0;e<4;e++) acc[i][j][e] = 0.0f;

    const int NC = K >> 5;                // K/32 chunks

    auto load_stage = [&](int kc, int s){
        const uint32_t st = sb + s*STAGE_BYTES;
        const long long k0 = (long long)kc << 5;
#pragma unroll
        for (int t=0;t<8;t++){
            int id    = tid + (t&1)*256;            // 0..511
            int plane = t>>1;                       // 0..3
            int r     = id >> 2;                    // 0..127
            int c16   = id & 3;                     // 16B unit within 64B row
            uint32_t dst = st + plane*PLANE_BYTES + r*80 + c16*16;
            const bf16* src;
            if      (plane==0) src = Ah + (long long)(rowBase+r)*K + k0 + c16*8;
            else if (plane==1) src = Al + (long long)(rowBase+r)*K + k0 + c16*8;
            else if (plane==2) src = Bh + (long long)(colBase+r)*K + k0 + c16*8;
            else               src = Bl + (long long)(colBase+r)*K + k0 + c16*8;
            cp16(dst, src);
        }
        cpcommit();
    };

    load_stage(0, 0);
    if (NC > 1) load_stage(1, 1);
    cpwait<1>();
    __syncthreads();

    for (int c=0; c<NC; c++){
        const int s = c & 1;
        const uint32_t st = sb + s*STAGE_BYTES;
        const uint32_t aBase = st + (uint32_t)((wm*64 + lr)*80 + lh*16);
        const uint32_t bBase = st + 2*PLANE_BYTES + (uint32_t)((wn*32 + lr)*80 + lh*16);

#pragma unroll
        for (int ks=0; ks<2; ks++){
            const uint32_t ko = ks*32;              // byte offset within row
            // B fragments for the whole warp tile (16 regs live)
            uint32_t bh[4][2], bl[4][2];
#pragma unroll
            for (int jj=0;jj<2;jj++){
                uint32_t t4[4];
                ldsm4(t4, bBase + ko + jj*16*80);
                bh[2*jj][0]=t4[0]; bh[2*jj+1][0]=t4[1];
                bh[2*jj][1]=t4[2]; bh[2*jj+1][1]=t4[3];
                ldsm4(t4, bBase + PLANE_BYTES + ko + jj*16*80);
                bl[2*jj][0]=t4[0]; bl[2*jj+1][0]=t4[1];
                bl[2*jj][1]=t4[2]; bl[2*jj+1][1]=t4[3];
            }
            // Stream A fragments per 16-row slab (8 regs live at a time)
#pragma unroll
            for (int i=0;i<4;i++){
                uint32_t a_h[4], a_l[4];
                ldsm4(a_h, aBase + ko + i*16*80);
                ldsm4(a_l, aBase + PLANE_BYTES + ko + i*16*80);
#pragma unroll
                for (int j=0;j<4;j++){
                    mma16816(acc[i][j], a_h, bh[j]);
                    mma16816(acc[i][j], a_h, bl[j]);
                    mma16816(acc[i][j], a_l, bh[j]);
                }
            }
        }

        if (c+1 < NC){
            __syncthreads();                       // all warps done reading stage s
            if (c+2 < NC){ load_stage(c+2, s); cpwait<1>(); }
            else         { cpwait<0>(); }
            __syncthreads();                       // next stage visible to all
        }
    }

    // ------------------------------- epilogue ------------------------------
    if (EPI<=3){
#pragma unroll
        for (int i=0;i<4;i++){
#pragma unroll
            for (int j=0;j<4;j++){
                const int r0 = rowBase + wm*64 + i*16 + g;
                const int c0 = colBase + wn*32 + j*8 + tg*2;
#pragma unroll
                for (int h=0;h<2;h++){
                    const int r = r0 + h*8;
                    float v0 = acc[i][j][2*h+0];
                    float v1 = acc[i][j][2*h+1];
                    if (EPI==0){
                        v0 = gelu_f(v0 + bias[c0]);
                        v1 = gelu_f(v1 + bias[c0+1]);
                        *(float2*)(Cf + (long long)r*N + c0) = make_float2(v0, v1);
                    } else if (EPI==1){
                        v0 += bias[c0]; v1 += bias[c0+1];
                        *(float2*)(Cf + (long long)r*N + c0) = make_float2(v0, v1);
                    } else if (EPI==2){
                        *(float2*)(Cf + (long long)r*N + c0) = make_float2(v0*alpha, v1*alpha);
                    } else {
                        const long long off = (long long)r*N + c0;
                        const float2 gg = *(const float2*)(gate + off);
                        float x0 = v0*gg.x, x1 = v1*gg.y;
                        *(uint32_t*)(Ch + off) = pack2(x0, x1);
                        *(uint32_t*)(Cl + off) = pack2(x0 - bf_hi(x0), x1 - bf_hi(x1));
                    }
                }
            }
        }
    } else {
        // EPI==4: gelu(acc+bias) -> transposed hi/lo planes [Bb][UVd][Ll].
        // Stage the 128x128 tile through smem (reusing pipeline buffers).
        __syncthreads();                          // all warps done with stages
        float* tb = (float*)smem;                 // [128 n][132 m] f32 = 67.6 KB
#pragma unroll
        for (int i=0;i<4;i++){
#pragma unroll
            for (int j=0;j<4;j++){
                const int cl0 = wn*32 + j*8 + tg*2;
                const int rl0 = wm*64 + i*16 + g;
#pragma unroll
                for (int h=0;h<2;h++){
                    const int rl = rl0 + h*8;
                    float x0 = gelu_f(acc[i][j][2*h+0] + bias[colBase+cl0]);
                    float x1 = gelu_f(acc[i][j][2*h+1] + bias[colBase+cl0+1]);
                    tb[cl0*132 + rl]     = x0;
                    tb[(cl0+1)*132 + rl] = x1;
                }
            }
        }
        __syncthreads();
        const int b  = rowBase >> 11;
        const int l0 = rowBase & (Ll-1);
#pragma unroll
        for (int i=0;i<16;i++){
            const int nl = wid*16 + i;
            float4 v = *(float4*)&tb[nl*132 + lane*4];
            long long off = ((long long)b*UVd + colBase + nl)*Ll + l0 + lane*4;
            *(uint2*)(Ch + off) = make_uint2(pack2(v.x,v.y), pack2(v.z,v.w));
            *(uint2*)(Cl + off) = make_uint2(pack2(v.x-bf_hi(v.x), v.y-bf_hi(v.y)),
                                             pack2(v.z-bf_hi(v.z), v.w-bf_hi(v.w)));
        }
    }
}

// --------------------------- small kernels ---------------------------------
__global__ void conv_hl(const float4* __restrict__ x, uint2* __restrict__ h,
                        uint2* __restrict__ l, int n4)
{
    int i = blockIdx.x*256 + threadIdx.x;
    if (i >= n4) return;
    float4 v = x[i];
    h[i] = make_uint2(pack2(v.x,v.y), pack2(v.z,v.w));
    l[i] = make_uint2(pack2(v.x-bf_hi(v.x),v.y-bf_hi(v.y)),
                      pack2(v.z-bf_hi(v.z),v.w-bf_hi(v.w)));
}

__global__ void convT_hl(const float* __restrict__ W, bf16* __restrict__ th,
                         bf16* __restrict__ tl, int Rw, int Cw)
{
    __shared__ float t[32][33];
    int rB = blockIdx.y*32, cB = blockIdx.x*32;
    t[threadIdx.y][threadIdx.x] = W[(long long)(rB+threadIdx.y)*Cw + cB + threadIdx.x];
    __syncthreads();
    float v = t[threadIdx.x][threadIdx.y];
    long long o = (long long)(cB+threadIdx.y)*Rw + rB + threadIdx.x;
    th[o] = __float2bfloat16(v);
    tl[o] = __float2bfloat16(v - bf_hi(v));
}

__global__ void rope_hl(const float* __restrict__ qk,
                        const float* __restrict__ gq, const float* __restrict__ betq,
                        const float* __restrict__ gk, const float* __restrict__ betk,
                        bf16* __restrict__ qh, bf16* __restrict__ ql,
                        bf16* __restrict__ kh, bf16* __restrict__ kl)
{
    int idx = blockIdx.x*256 + threadIdx.x;
    if (idx >= MT*64) return;
    int p = idx&63, row = idx>>6, l = row&(Ll-1);
    float invf = powf(10000.0f, -(float)(2*p)/128.0f);
    float s, c; sincosf((float)l*invf, &s, &c);
    float2 v = ((const float2*)qk)[idx];
    float q1 = v.x*gq[2*p]+betq[2*p], q2 = v.y*gq[2*p+1]+betq[2*p+1];
    float a = q1*c-q2*s, b = q1*s+q2*c;
    ((uint32_t*)qh)[idx] = pack2(a,b);
    ((uint32_t*)ql)[idx] = pack2(a-bf_hi(a), b-bf_hi(b));
    float k1 = v.x*gk[2*p]+betk[2*p], k2 = v.y*gk[2*p+1]+betk[2*p+1];
    a = k1*c-k2*s; b = k1*s+k2*c;
    ((uint32_t*)kh)[idx] = pack2(a,b);
    ((uint32_t*)kl)[idx] = pack2(a-bf_hi(a), b-bf_hi(b));
}

__global__ void softmax_hl(float* __restrict__ attn,
                           bf16* __restrict__ ah, bf16* __restrict__ al)
{
    const long long row = blockIdx.x;
    float* p = attn + row*Ll;
    const int tid = threadIdx.x;
    __shared__ float red[256];

    float m = -INFINITY;
    for (int i=tid;i<Ll;i+=256) m = fmaxf(m, p[i]);
    red[tid]=m; __syncthreads();
    for (int s=128;s>0;s>>=1){ if(tid<s) red[tid]=fmaxf(red[tid],red[tid+s]); __syncthreads(); }
    m = red[0]; __syncthreads();

    float sum = 0.0f;
    for (int i=tid;i<Ll;i+=256){ float e=__expf(p[i]-m); p[i]=e; sum+=e; }
    red[tid]=sum; __syncthreads();
    for (int s=128;s>0;s>>=1){ if(tid<s) red[tid]+=red[tid+s]; __syncthreads(); }
    float r = 1.0f/red[0];

    uint32_t* wh = (uint32_t*)ah + row*(Ll/2);
    uint32_t* wl = (uint32_t*)al + row*(Ll/2);
    for (int i=tid;i<Ll/2;i+=256){
        float2 e = ((float2*)p)[i];
        float v0=e.x*r, v1=e.y*r;
        ((float2*)p)[i] = make_float2(v0,v1);
        wh[i] = pack2(v0,v1);
        wl[i] = pack2(v0-bf_hi(v0), v1-bf_hi(v1));
    }
}

// ---------------------------------------------------------------------------
extern "C" void kernel_launch(void* const* d_in, const int* in_sizes, int n_in,
                              void* d_out, int out_size)
{
    const float* u       = (const float*)d_in[0];
    const float* queries = (const float*)d_in[1];
    const float* values  = (const float*)d_in[3];
    const float* Wqk  = (const float*)d_in[4];
    const float* bqk  = (const float*)d_in[5];
    const float* gq   = (const float*)d_in[6];
    const float* betq = (const float*)d_in[7];
    const float* gk   = (const float*)d_in[8];
    const float* betk = (const float*)d_in[9];
    const float* Wv   = (const float*)d_in[10];
    const float* bv   = (const float*)d_in[11];
    const float* Wu   = (const float*)d_in[12];
    const float* bu   = (const float*)d_in[13];
    const float* Wo   = (const float*)d_in[14];
    const float* bo   = (const float*)d_in[15];

    float *qk, *ug, *attn_s;
    bf16 *qh,*ql,*kh,*kl,*Qh,*Ql,*Vh,*Vl,*Uh,*Ul;
    bf16 *WqkTh,*WqkTl,*WvTh,*WvTl,*WuTh,*WuTl,*WoTh,*WoTl;
    bf16 *vTh,*vTl,*ah,*al,*gh,*gl;
    cudaGetSymbolAddress((void**)&qk, g_qk);
    cudaGetSymbolAddress((void**)&qh, g_qh);   cudaGetSymbolAddress((void**)&ql, g_ql);
    cudaGetSymbolAddress((void**)&kh, g_kh);   cudaGetSymbolAddress((void**)&kl, g_kl);
    cudaGetSymbolAddress((void**)&Qh, g_Qh);   cudaGetSymbolAddress((void**)&Ql, g_Ql);
    cudaGetSymbolAddress((void**)&Vh, g_Vh);   cudaGetSymbolAddress((void**)&Vl, g_Vl);
    cudaGetSymbolAddress((void**)&Uh, g_Uh);   cudaGetSymbolAddress((void**)&Ul, g_Ul);
    cudaGetSymbolAddress((void**)&WqkTh, g_WqkTh); cudaGetSymbolAddress((void**)&WqkTl, g_WqkTl);
    cudaGetSymbolAddress((void**)&WvTh, g_WvTh);   cudaGetSymbolAddress((void**)&WvTl, g_WvTl);
    cudaGetSymbolAddress((void**)&WuTh, g_WuTh);   cudaGetSymbolAddress((void**)&WuTl, g_WuTl);
    cudaGetSymbolAddress((void**)&WoTh, g_WoTh);   cudaGetSymbolAddress((void**)&WoTl, g_WoTl);
    cudaGetSymbolAddress((void**)&vTh, g_vTh);     cudaGetSymbolAddress((void**)&vTl, g_vTl);
    cudaGetSymbolAddress((void**)&ug, g_ug);
    cudaGetSymbolAddress((void**)&attn_s, g_attn);
    cudaGetSymbolAddress((void**)&ah, g_ah);   cudaGetSymbolAddress((void**)&al, g_al);
    cudaGetSymbolAddress((void**)&gh, g_gh);   cudaGetSymbolAddress((void**)&gl, g_gl);

    float* o_out = (float*)d_out;
    float* attn = ((long long)out_size >= O_ELEMS + ATTN_ELEMS)
                      ? (o_out + O_ELEMS) : attn_s;

    cudaFuncSetAttribute(gemm_hmma<0>, cudaFuncAttributeMaxDynamicSharedMemorySize, SMEM_BYTES);
    cudaFuncSetAttribute(gemm_hmma<1>, cudaFuncAttributeMaxDynamicSharedMemorySize, SMEM_BYTES);
    cudaFuncSetAttribute(gemm_hmma<2>, cudaFuncAttributeMaxDynamicSharedMemorySize, SMEM_BYTES);
    cudaFuncSetAttribute(gemm_hmma<3>, cudaFuncAttributeMaxDynamicSharedMemorySize, SMEM_BYTES);
    cudaFuncSetAttribute(gemm_hmma<4>, cudaFuncAttributeMaxDynamicSharedMemorySize, SMEM_BYTES);

    const long long sQK = (long long)Ll*QKd, sAT = (long long)Ll*Ll;
    const long long sUV = (long long)Ll*UVd, sVT = (long long)UVd*Ll;
    const int n4 = MT*Dd/4;

    // Setup ordered so ncu (-s 5 -c 1) profiles the BIG ug GEMM (launch #6):
    // 0..4: conv(u), convT(Wu), conv(q), convT(Wqk), conv(v)
    conv_hl<<<(n4+255)/256,256>>>((const float4*)u,      (uint2*)Uh,(uint2*)Ul,n4);
    convT_hl<<<dim3(UVd/32, Dd/32), dim3(32,32)>>>(Wu,  WuTh,  WuTl,  Dd, UVd);
    conv_hl<<<(n4+255)/256,256>>>((const float4*)queries,(uint2*)Qh,(uint2*)Ql,n4);
    convT_hl<<<dim3(QKd/32, Dd/32), dim3(32,32)>>>(Wqk, WqkTh, WqkTl, Dd, QKd);
    conv_hl<<<(n4+255)/256,256>>>((const float4*)values, (uint2*)Vh,(uint2*)Vl,n4);

    // 5) ug = gelu(u @ Wu + bu)                    [16384 x 2048]  <- profiled
    gemm_hmma<0><<<dim3(UVd/128,128,1),256,SMEM_BYTES>>>(Dd, UVd, Uh,Ul,0, WuTh,WuTl,0,
        ug,0, nullptr,nullptr,0, bu, nullptr,0, 0.f);

    convT_hl<<<dim3(UVd/32, Dd/32), dim3(32,32)>>>(Wv,  WvTh,  WvTl,  Dd, UVd);
    convT_hl<<<dim3(Dd/32, UVd/32), dim3(32,32)>>>(Wo,  WoTh,  WoTl,  UVd, Dd);

    // qk = gelu(queries @ Wqk + bqk)               [16384 x 128]
    gemm_hmma<0><<<dim3(1,128,1),256,SMEM_BYTES>>>(Dd, QKd, Qh,Ql,0, WqkTh,WqkTl,0,
        qk,0, nullptr,nullptr,0, bqk, nullptr,0, 0.f);
    // rope -> q/k hi-lo planes
    rope_hl<<<(MT*64+255)/256,256>>>(qk, gq,betq, gk,betk, qh,ql, kh,kl);
    // v^T planes = gelu(values @ Wv + bv)^T        [8][2048][2048]
    gemm_hmma<4><<<dim3(UVd/128,128,1),256,SMEM_BYTES>>>(Dd, UVd, Vh,Vl,0, WvTh,WvTl,0,
        nullptr,0, vTh,vTl,0, bv, nullptr,0, 0.f);
    // scores = q @ k^T / sqrt(128)                 [8 x 2048 x 2048]
    gemm_hmma<2><<<dim3(Ll/128,Ll/128,Bb),256,SMEM_BYTES>>>(QKd, Ll, qh,ql,sQK, kh,kl,sQK,
        attn,sAT, nullptr,nullptr,0, nullptr, nullptr,0, 0.08838834764831845f);
    // softmax rows -> attn f32 + hi/lo planes
    softmax_hl<<<MT,256>>>(attn, ah, al);
    // gated planes = ug * (attn @ v)               [8 x 2048 x 2048]
    gemm_hmma<3><<<dim3(UVd/128,Ll/128,Bb),256,SMEM_BYTES>>>(Ll, UVd, ah,al,sAT, vTh,vTl,sVT,
        nullptr,0, gh,gl,sUV, nullptr, ug,sUV, 0.f);
    // o = gated @ Wo + bo                          [16384 x 1024]
    gemm_hmma<1><<<dim3(Dd/128,128,1),256,SMEM_BYTES>>>(UVd, Dd, gh,gl,0, WoTh,WoTl,0,
        o_out,0, nullptr,nullptr,0, bo, nullptr,0, 0.f);
}